// round 15
// baseline (speedup 1.0000x reference)
#include <cuda_runtime.h>
#include <cuda_bf16.h>

#define NLAT 46
#define NLON 90
#define CH   256
#define SPX  (NLAT * NLON)   // 4140 spatial points

// Heavy rows: 0, 1, 44, 45 (pole rows + rows containing a full pole circle)
#define HEAVY_BLOCKS (4 * NLON)                 // 360
#define LIGHT_BEG    (2 * NLON)                 // 180
#define LIGHT_END    (44 * NLON)                // 3960
#define LIGHT_BLOCKS ((LIGHT_END - LIGHT_BEG + 7) / 8)   // 473

#define MAXNNZ 4096

// Projection GEMM tiling
#define BM 64
#define BN 128
#define BK 16
#define ST 20    // smem row stride in floats (pad for conflict-free frags)

// Scratch
__device__ float g_qc[CH * SPX];       // q channel-major [c][s]
__device__ float g_kc[CH * SPX];       // k channel-major [c][s]
__device__ float g_v [SPX * CH];       // v spatial-major [s][c]
__device__ float g_s [MAXNNZ * NLON];  // scores S[n][wo]
__device__ int   g_off[NLAT + 1];

__device__ __forceinline__ unsigned f2tf(float x) {
    unsigned r;
    asm("cvt.rna.tf32.f32 %0, %1;" : "=r"(r) : "f"(x));
    return r;
}

__device__ __forceinline__ void mma_tf32(float c[4], const unsigned a[4],
                                         const unsigned b[2]) {
    asm("mma.sync.aligned.m16n8k8.row.col.f32.tf32.tf32.f32 "
        "{%0,%1,%2,%3}, {%4,%5,%6,%7}, {%8,%9}, {%0,%1,%2,%3};"
        : "+f"(c[0]), "+f"(c[1]), "+f"(c[2]), "+f"(c[3])
        : "r"(a[0]), "r"(a[1]), "r"(a[2]), "r"(a[3]), "r"(b[0]), "r"(b[1]));
}

// ---------------------------------------------------------------------------
// Tensor-core projection GEMM (q,k,v by blockIdx.z) with 3xTF32 split:
//   out = W @ X + b ;  X: [CH][SPX], W: [CH][CH] row-major (= B col-major).
// A[s][c] = X^T staged via smem transpose.  hi/lo tf32 planes built at fill
// time so the mainloop is LDS + MMA only.  8 warps = 4(M)x2(N), warp tile
// 16x64.  q,k written channel-major [c][s]; v spatial-major [s][c].
// Block (0,0,0) also computes segment offsets.
// ---------------------------------------------------------------------------
__global__ void __launch_bounds__(256) proj_kernel(
    const float* __restrict__ qo, const float* __restrict__ ki,
    const float* __restrict__ vi,
    const float* __restrict__ q_w, const float* __restrict__ k_w,
    const float* __restrict__ v_w,
    const float* __restrict__ q_b, const float* __restrict__ k_b,
    const float* __restrict__ v_b,
    const int* __restrict__ row_ids, int nnz)
{
    const int which = blockIdx.z;
    const float* X    = (which == 0) ? qo  : (which == 1) ? ki  : vi;
    const float* W    = (which == 0) ? q_w : (which == 1) ? k_w : v_w;
    const float* bias = (which == 0) ? q_b : (which == 1) ? k_b : v_b;
    float* out        = (which == 0) ? g_qc : (which == 1) ? g_kc : g_v;

    const int tid = threadIdx.x;

    if (which == 0 && blockIdx.x == 0 && blockIdx.y == 0 && tid <= NLAT) {
        int lo = 0, hi = nnz;
        while (lo < hi) {
            int mid = (lo + hi) >> 1;
            if (row_ids[mid] < tid) lo = mid + 1; else hi = mid;
        }
        g_off[tid] = lo;
    }

    __shared__ __align__(16) unsigned XsH[BM * ST];
    __shared__ __align__(16) unsigned XsL[BM * ST];
    __shared__ __align__(16) unsigned WsH[BN * ST];
    __shared__ __align__(16) unsigned WsL[BN * ST];

    const int s0 = blockIdx.x * BM;
    const int n0 = blockIdx.y * BN;

    const int warp = tid >> 5;
    const int lane = tid & 31;
    const int wm   = warp >> 1;        // 0..3 : m offset wm*16
    const int wn   = warp & 1;         // 0..1 : n offset wn*64
    const int g    = lane >> 2;        // 0..7
    const int t    = lane & 3;         // 0..3

    // fill-stage indices
    const int xsm = tid & 63;          // spatial row 0..63
    const int xkh = tid >> 6;          // 0..3 -> k base *4
    const int wnr = tid >> 1;          // 0..127 (W row)
    const int wch = (tid & 1) * 8;     // 0 or 8

    float acc[8][4] = {};              // nf = 0..7

    for (int c0 = 0; c0 < CH; c0 += BK) {
        // --- fill XsH/XsL : Xs[sm][k] = X[(c0+k)*SPX + s0+sm]
        {
            const int s = s0 + xsm;
            unsigned h[4], l[4];
            #pragma unroll
            for (int j = 0; j < 4; ++j) {
                float x = (s < SPX) ? X[(c0 + xkh * 4 + j) * SPX + s] : 0.0f;
                h[j] = f2tf(x);
                l[j] = f2tf(x - __uint_as_float(h[j]));
            }
            *(uint4*)&XsH[xsm * ST + xkh * 4] = make_uint4(h[0], h[1], h[2], h[3]);
            *(uint4*)&XsL[xsm * ST + xkh * 4] = make_uint4(l[0], l[1], l[2], l[3]);
        }
        // --- fill WsH/WsL : Ws[n][k] = W[(n0+n)*CH + c0+k]
        {
            const float4* wp = (const float4*)&W[(n0 + wnr) * CH + c0 + wch];
            float4 wa = wp[0], wb = wp[1];
            float wv[8] = {wa.x, wa.y, wa.z, wa.w, wb.x, wb.y, wb.z, wb.w};
            unsigned h[8], l[8];
            #pragma unroll
            for (int j = 0; j < 8; ++j) {
                h[j] = f2tf(wv[j]);
                l[j] = f2tf(wv[j] - __uint_as_float(h[j]));
            }
            *(uint4*)&WsH[wnr * ST + wch]     = make_uint4(h[0], h[1], h[2], h[3]);
            *(uint4*)&WsH[wnr * ST + wch + 4] = make_uint4(h[4], h[5], h[6], h[7]);
            *(uint4*)&WsL[wnr * ST + wch]     = make_uint4(l[0], l[1], l[2], l[3]);
            *(uint4*)&WsL[wnr * ST + wch + 4] = make_uint4(l[4], l[5], l[6], l[7]);
        }
        __syncthreads();

        #pragma unroll
        for (int kc = 0; kc < 2; ++kc) {
            // A fragment: rows wm*16+g(+8), cols kc*8 + t(+4)
            unsigned ah[4], al[4];
            {
                const int base = (wm * 16) * ST + kc * 8;
                ah[0] = XsH[base + g * ST + t];
                ah[1] = XsH[base + (g + 8) * ST + t];
                ah[2] = XsH[base + g * ST + t + 4];
                ah[3] = XsH[base + (g + 8) * ST + t + 4];
                al[0] = XsL[base + g * ST + t];
                al[1] = XsL[base + (g + 8) * ST + t];
                al[2] = XsL[base + g * ST + t + 4];
                al[3] = XsL[base + (g + 8) * ST + t + 4];
            }
            #pragma unroll
            for (int nf = 0; nf < 8; ++nf) {
                const int base = (wn * 64 + nf * 8) * ST + kc * 8;
                unsigned bh[2], bl[2];
                bh[0] = WsH[base + g * ST + t];       // b0: k=t,   n=g
                bh[1] = WsH[base + g * ST + t + 4];   // b1: k=t+4, n=g
                bl[0] = WsL[base + g * ST + t];
                bl[1] = WsL[base + g * ST + t + 4];
                mma_tf32(acc[nf], ah, bh);
                mma_tf32(acc[nf], ah, bl);
                mma_tf32(acc[nf], al, bh);
            }
        }
        __syncthreads();
    }

    // --- epilogue ---
    const int sA = s0 + wm * 16 + g;
    const int sB = sA + 8;

    if (which == 2) {
        // v: spatial-major [s][c]
        #pragma unroll
        for (int nf = 0; nf < 8; ++nf) {
            const int c = n0 + wn * 64 + nf * 8 + 2 * t;
            const float b0 = __ldg(&bias[c]);
            const float b1 = __ldg(&bias[c + 1]);
            if (sA < SPX) {
                float2 o = make_float2(acc[nf][0] + b0, acc[nf][1] + b1);
                *(float2*)&out[sA * CH + c] = o;
            }
            if (sB < SPX) {
                float2 o = make_float2(acc[nf][2] + b0, acc[nf][3] + b1);
                *(float2*)&out[sB * CH + c] = o;
            }
        }
    } else {
        // q,k: channel-major [c][s]
        #pragma unroll
        for (int nf = 0; nf < 8; ++nf) {
            const int c = n0 + wn * 64 + nf * 8 + 2 * t;
            const float b0 = __ldg(&bias[c]);
            const float b1 = __ldg(&bias[c + 1]);
            if (sA < SPX) {
                out[c * SPX + sA]       = acc[nf][0] + b0;
                out[(c + 1) * SPX + sA] = acc[nf][1] + b1;
            }
            if (sB < SPX) {
                out[c * SPX + sB]       = acc[nf][2] + b0;
                out[(c + 1) * SPX + sB] = acc[nf][3] + b1;
            }
        }
    }
}

// ---------------------------------------------------------------------------
// Score pass (r11 exact — measured good):
//   S[n][wo] = exp(q[t_n,wo] . k[h_n,(w_n+wo)%NLON]) * quad[h_n]
// One warp per (neighbor n, 32-wide wo block). Lanes span wo -> coalesced.
// ---------------------------------------------------------------------------
__global__ void __launch_bounds__(256) score_kernel(
    const int*   __restrict__ row_ids,
    const int*   __restrict__ col_idx,
    const float* __restrict__ quad,
    int nnz)
{
    const int w    = (int)((blockIdx.x * 256 + threadIdx.x) >> 5);
    const int lane = threadIdx.x & 31;
    const int n    = w / 3;
    const int wb   = w - n * 3;
    if (n >= nnz) return;

    const int t   = __ldg(&row_ids[n]);
    const int ci  = __ldg(&col_idx[n]);
    const int hi  = ci / NLON;
    const int wi0 = ci - hi * NLON;

    const int wo  = wb * 32 + lane;
    const bool act = (wo < NLON);
    const int woc = act ? wo : 0;
    int wi = wi0 + woc;
    if (wi >= NLON) wi -= NLON;

    const float* qp = g_qc + t * NLON + woc;
    const float* kp = g_kc + hi * NLON + wi;

    float p0 = 0.f, p1 = 0.f, p2 = 0.f, p3 = 0.f;
    #pragma unroll 4
    for (int c = 0; c < CH; c += 4) {
        p0 += qp[0 * SPX] * kp[0 * SPX];
        p1 += qp[1 * SPX] * kp[1 * SPX];
        p2 += qp[2 * SPX] * kp[2 * SPX];
        p3 += qp[3 * SPX] * kp[3 * SPX];
        qp += 4 * SPX; kp += 4 * SPX;
    }
    float e = __expf((p0 + p1) + (p2 + p3)) * __ldg(&quad[hi]);
    if (act) g_s[n * NLON + wo] = e;
}

// ---------------------------------------------------------------------------
// Output pass (r11 exact — measured good)
// ---------------------------------------------------------------------------
__device__ __forceinline__ void out_step(
    int n, int wo, int lane,
    const int* __restrict__ col_idx,
    float& d, float4& a0, float4& a1)
{
    int ci = __ldg(&col_idx[n]);
    int hi = ci / NLON;
    int wi = ci - hi * NLON + wo;
    if (wi >= NLON) wi -= NLON;
    int base = (hi * NLON + wi) * CH;

    float e = __ldg(&g_s[n * NLON + wo]);

    const float4* vv = (const float4*)(g_v + base);
    float4 v0 = vv[lane];
    float4 v1 = vv[lane + 32];

    d += e;
    a0.x += e * v0.x;  a0.y += e * v0.y;
    a0.z += e * v0.z;  a0.w += e * v0.w;
    a1.x += e * v1.x;  a1.y += e * v1.y;
    a1.z += e * v1.z;  a1.w += e * v1.w;
}

__global__ void __launch_bounds__(256) attn_out_kernel(
    const int* __restrict__ col_idx,
    float*     __restrict__ out)
{
    __shared__ float smem[2304];   // heavy: [8][256]+[8] | light: [256][9]

    const int warp = threadIdx.x >> 5;
    const int lane = threadIdx.x & 31;

    if (blockIdx.x < HEAVY_BLOCKS) {
        const int bi = blockIdx.x;
        int r = bi / NLON;                             // 0..3
        const int t  = (r < 2) ? r : (NLAT - 4 + r);   // 0,1,44,45
        const int wo = bi - r * NLON;
        const int pos = t * NLON + wo;

        float d = 0.0f;
        float4 a0 = make_float4(0.f, 0.f, 0.f, 0.f);
        float4 a1 = make_float4(0.f, 0.f, 0.f, 0.f);

        const int beg = g_off[t];
        const int end = g_off[t + 1];

        #pragma unroll 2
        for (int n = beg + warp; n < end; n += 8)
            out_step(n, wo, lane, col_idx, d, a0, a1);

        float* sb = smem + warp * 256;
        *(float4*)&sb[lane * 4]       = a0;
        *(float4*)&sb[128 + lane * 4] = a1;
        if (lane == 0) smem[2048 + warp] = d;
        __syncthreads();

        const int c = threadIdx.x;
        float s = 0.0f, dt = 0.0f;
        #pragma unroll
        for (int w = 0; w < 8; ++w) s  += smem[w * 256 + c];
        #pragma unroll
        for (int w = 0; w < 8; ++w) dt += smem[2048 + w];
        out[c * SPX + pos] = s / dt;
    } else {
        const int pos0 = LIGHT_BEG + (blockIdx.x - HEAVY_BLOCKS) * 8;
        const int gw   = pos0 + warp;

        if (gw < LIGHT_END) {
            const int t  = gw / NLON;
            const int wo = gw - t * NLON;

            float d = 0.0f;
            float4 a0 = make_float4(0.f, 0.f, 0.f, 0.f);
            float4 a1 = make_float4(0.f, 0.f, 0.f, 0.f);

            const int beg = g_off[t];
            const int end = g_off[t + 1];

            #pragma unroll 2
            for (int n = beg; n < end; ++n)
                out_step(n, wo, lane, col_idx, d, a0, a1);

            const float inv = 1.0f / d;
            const int c0 = lane * 4;
            smem[(c0 + 0) * 9 + warp] = a0.x * inv;
            smem[(c0 + 1) * 9 + warp] = a0.y * inv;
            smem[(c0 + 2) * 9 + warp] = a0.z * inv;
            smem[(c0 + 3) * 9 + warp] = a0.w * inv;
            smem[(c0 + 128) * 9 + warp] = a1.x * inv;
            smem[(c0 + 129) * 9 + warp] = a1.y * inv;
            smem[(c0 + 130) * 9 + warp] = a1.z * inv;
            smem[(c0 + 131) * 9 + warp] = a1.w * inv;
        }
        __syncthreads();

        const int p  = threadIdx.x & 7;
        const int cb = threadIdx.x >> 3;
        if (pos0 + p < LIGHT_END) {
            #pragma unroll
            for (int j = 0; j < 8; ++j) {
                int c = cb + j * 32;
                out[c * SPX + pos0 + p] = smem[c * 9 + p];
            }
        }
    }
}

// ---------------------------------------------------------------------------
extern "C" void kernel_launch(void* const* d_in, const int* in_sizes, int n_in,
                              void* d_out, int out_size)
{
    const float* qo   = (const float*)d_in[0];
    const float* ki   = (const float*)d_in[1];
    const float* vi   = (const float*)d_in[2];
    const float* q_w  = (const float*)d_in[3];
    const float* k_w  = (const float*)d_in[4];
    const float* v_w  = (const float*)d_in[5];
    const float* q_b  = (const float*)d_in[6];
    const float* k_b  = (const float*)d_in[7];
    const float* v_b  = (const float*)d_in[8];
    const float* quad = (const float*)d_in[9];
    const int* row_ids = (const int*)d_in[10];
    const int* col_idx = (const int*)d_in[11];
    const int nnz = in_sizes[10];

    float* out = (float*)d_out;

    dim3 gg((SPX + BM - 1) / BM, CH / BN, 3);   // (65, 2, 3)
    proj_kernel<<<gg, 256>>>(qo, ki, vi, q_w, k_w, v_w, q_b, k_b, v_b,
                             row_ids, nnz);

    int score_warps = 3 * nnz;
    score_kernel<<<(score_warps + 7) / 8, 256>>>(row_ids, col_idx, quad, nnz);

    attn_out_kernel<<<HEAVY_BLOCKS + LIGHT_BLOCKS, 256>>>(col_idx, out);
}